// round 8
// baseline (speedup 1.0000x reference)
#include <cuda_runtime.h>
#include <cuda_bf16.h>
#include <math.h>
#include <stdint.h>

// Problem constants
#define BATCH 32
#define SEQ   1024
#define HID   512
#define NH    8
#define DH    64                 // head dim = 512/8
#define ROWS  (BATCH*SEQ)        // 32768
#define NEGV  (-4294967295.0f)   // -(2^32)+1, matches reference mask value

// ---------------- scratch (static device globals; no allocations) ----------
__device__ uint16_t g_q[(size_t)ROWS * HID];
__device__ uint16_t g_k[(size_t)ROWS * HID];
__device__ uint16_t g_v[(size_t)ROWS * HID];
__device__ float    g_qmask[ROWS];
__device__ float    g_kmask[ROWS];

__device__ __forceinline__ uint32_t pack_bf16(float lo, float hi) {
    __nv_bfloat162 p = __floats2bfloat162_rn(lo, hi);   // x = lo (low half)
    return *reinterpret_cast<uint32_t*>(&p);
}

#define MMA_BF16(acc, a, b)                                              \
    asm volatile(                                                        \
        "mma.sync.aligned.m16n8k16.row.col.f32.bf16.bf16.f32 "           \
        "{%0,%1,%2,%3}, {%4,%5,%6,%7}, {%8,%9}, {%0,%1,%2,%3};"          \
        : "+f"((acc)[0]), "+f"((acc)[1]), "+f"((acc)[2]), "+f"((acc)[3]) \
        : "r"((a)[0]), "r"((a)[1]), "r"((a)[2]), "r"((a)[3]),            \
          "r"((b)[0]), "r"((b)[1]))

#define LDSM_X4(r0, r1, r2, r3, addr)                                    \
    asm volatile(                                                        \
        "ldmatrix.sync.aligned.m8n8.x4.shared.b16 {%0,%1,%2,%3}, [%4];"  \
        : "=r"(r0), "=r"(r1), "=r"(r2), "=r"(r3) : "r"(addr))

#define LDSM_X4_T(r0, r1, r2, r3, addr)                                  \
    asm volatile(                                                        \
        "ldmatrix.sync.aligned.m8n8.x4.trans.shared.b16 {%0,%1,%2,%3}, [%4];" \
        : "=r"(r0), "=r"(r1), "=r"(r2), "=r"(r3) : "r"(addr))

// ---------------- kernel 1: masks -----------------------------------------
__global__ void mask_kernel(const float* __restrict__ queries,
                            const float* __restrict__ keys) {
    int row  = blockIdx.x * 8 + (threadIdx.x >> 5);   // 0 .. 2*ROWS-1
    int lane = threadIdx.x & 31;
    const float* src;
    float* dst;
    if (row < ROWS) { src = queries + (size_t)row * HID; dst = g_qmask + row; }
    else            { src = keys + (size_t)(row - ROWS) * HID; dst = g_kmask + (row - ROWS); }
    float s = 0.f;
#pragma unroll
    for (int i = 0; i < HID / 32; i++) s += src[lane + i * 32];
#pragma unroll
    for (int off = 16; off > 0; off >>= 1) s += __shfl_xor_sync(0xFFFFFFFFu, s, off);
    if (lane == 0) *dst = (s != 0.0f) ? 1.0f : 0.0f;
}

// ---------------- kernel 2: QKV projection GEMM (bf16 tensor cores) --------
// (unchanged from R7 — passing at ~180us)
#define GAP 72     // As pitch (bf16 units)
#define GBP 136    // Bs pitch (bf16 units)

__global__ __launch_bounds__(256, 2)
void gemm_qkv(const float* __restrict__ queries, const float* __restrict__ keys,
              const float* __restrict__ Wq, const float* __restrict__ bq,
              const float* __restrict__ Wk, const float* __restrict__ bk,
              const float* __restrict__ Wv, const float* __restrict__ bv) {
    const float* A; const float* W; const float* bias; uint16_t* C;
    if (blockIdx.z == 0)      { A = queries; W = Wq; bias = bq; C = g_q; }
    else if (blockIdx.z == 1) { A = keys;    W = Wk; bias = bk; C = g_k; }
    else                      { A = keys;    W = Wv; bias = bv; C = g_v; }

    __shared__ uint16_t As[128 * GAP];
    __shared__ uint16_t Bs[64 * GBP];

    const int tid    = threadIdx.x;
    const int wid    = tid >> 5;
    const int lane   = tid & 31;
    const int g      = lane >> 2;
    const int t      = lane & 3;
    const int warp_m = (wid & 1) * 64;
    const int warp_n = (wid >> 1) * 32;
    const int m0     = blockIdx.y * 128;
    const int n0     = blockIdx.x * 128;

    float acc[4][4][4];
#pragma unroll
    for (int mt = 0; mt < 4; mt++)
#pragma unroll
        for (int nt = 0; nt < 4; nt++)
#pragma unroll
            for (int c = 0; c < 4; c++) acc[mt][nt][c] = 0.f;

    for (int k0 = 0; k0 < HID; k0 += 64) {
#pragma unroll
        for (int i = 0; i < 8; i++) {
            int idx = tid + i * 256;
            int row = idx >> 4;
            int col = (idx & 15) * 4;
            float4 v = *(const float4*)&A[(size_t)(m0 + row) * HID + k0 + col];
            uint32_t* d = (uint32_t*)&As[row * GAP + col];
            d[0] = pack_bf16(v.x, v.y);
            d[1] = pack_bf16(v.z, v.w);
        }
#pragma unroll
        for (int i = 0; i < 8; i++) {
            int idx = tid + i * 256;
            int row = idx >> 5;
            int col = (idx & 31) * 4;
            float4 v = *(const float4*)&W[(size_t)(k0 + row) * HID + n0 + col];
            uint32_t* d = (uint32_t*)&Bs[row * GBP + col];
            d[0] = pack_bf16(v.x, v.y);
            d[1] = pack_bf16(v.z, v.w);
        }
        __syncthreads();

#pragma unroll
        for (int ks = 0; ks < 64; ks += 16) {
            uint32_t af[4][4];
#pragma unroll
            for (int mt = 0; mt < 4; mt++) {
                int am = warp_m + mt * 16 + g;
                af[mt][0] = *(uint32_t*)&As[am * GAP + ks + 2 * t];
                af[mt][1] = *(uint32_t*)&As[(am + 8) * GAP + ks + 2 * t];
                af[mt][2] = *(uint32_t*)&As[am * GAP + ks + 8 + 2 * t];
                af[mt][3] = *(uint32_t*)&As[(am + 8) * GAP + ks + 8 + 2 * t];
            }
            uint32_t bf[4][2];
#pragma unroll
            for (int nt = 0; nt < 4; nt++) {
                int bn = warp_n + nt * 8 + g;
                bf[nt][0] = (uint32_t)Bs[(ks + 2 * t) * GBP + bn]
                          | ((uint32_t)Bs[(ks + 2 * t + 1) * GBP + bn] << 16);
                bf[nt][1] = (uint32_t)Bs[(ks + 2 * t + 8) * GBP + bn]
                          | ((uint32_t)Bs[(ks + 2 * t + 9) * GBP + bn] << 16);
            }
#pragma unroll
            for (int mt = 0; mt < 4; mt++)
#pragma unroll
                for (int nt = 0; nt < 4; nt++)
                    MMA_BF16(acc[mt][nt], af[mt], bf[nt]);
        }
        __syncthreads();
    }

#pragma unroll
    for (int mt = 0; mt < 4; mt++) {
        int row0 = m0 + warp_m + mt * 16 + g;
#pragma unroll
        for (int nt = 0; nt < 4; nt++) {
            int col = n0 + warp_n + nt * 8 + t * 2;
            float b0 = bias[col], b1 = bias[col + 1];
            *(uint32_t*)&C[(size_t)row0 * HID + col] =
                pack_bf16(acc[mt][nt][0] + b0, acc[mt][nt][1] + b1);
            *(uint32_t*)&C[(size_t)(row0 + 8) * HID + col] =
                pack_bf16(acc[mt][nt][2] + b0, acc[mt][nt][3] + b1);
        }
    }
}

// ---------------- kernel 3: flash attention (bf16 + ldmatrix) --------------
// grid (8 q-tiles of 128, 32 batch, 8 heads), 256 threads = 8 warps x 16 rows.
// K b-frags: non-trans ldmatrix.x4 from [key][d]; V b-frags: trans ldmatrix.x4.
// Per-warp causal tile skip.
#define KP 72      // K/V smem pitch (bf16 units): rows step 36 banks == 4 mod 32

__global__ __launch_bounds__(256)
void attn_kernel(const float* __restrict__ queries, float* __restrict__ out) {
    const int qt = blockIdx.x;   // 0..7  (128-row q tile)
    const int b  = blockIdx.y;   // 0..31
    const int h  = blockIdx.z;   // 0..7

    __shared__ uint16_t Ks[64 * KP];   // [key][d] bf16
    __shared__ uint16_t Vs[64 * KP];   // [key][d] bf16
    __shared__ float    kms[64];

    const int tid  = threadIdx.x;
    const int w    = tid >> 5;
    const int lane = tid & 31;
    const int g    = lane >> 2;
    const int t    = lane & 3;

    const size_t headoff = (size_t)b * SEQ * HID + h * DH;
    const uint16_t* qbase = g_q + headoff;
    const uint16_t* kbase = g_k + headoff;
    const uint16_t* vbase = g_v + headoff;

    const int wmin  = qt * 128 + w * 16;       // warp's min q row (local)
    const int wmax  = wmin + 15;               // warp's max q row
    const int row_l = wmin + g;                // this thread's frag row

    // ldmatrix source addresses (shared-space u32), fixed per thread
    const uint32_t ks_base = (uint32_t)__cvta_generic_to_shared(Ks);
    const uint32_t vs_base = (uint32_t)__cvta_generic_to_shared(Vs);
    // K non-trans x4: tile = lane>>3 selects d-offset; row = key = nt*8 + (lane&7)
    const uint32_t k_addr0 = ks_base + (uint32_t)(((lane & 7) * KP + (lane >> 3) * 8) * 2);
    // V trans x4: tile = lane>>3: bit0 -> key+8, bit1 -> d+8; row = key
    const uint32_t v_addr0 = vs_base +
        (uint32_t)(((((lane >> 3) & 1) * 8 + (lane & 7)) * KP + ((lane >> 4) * 8)) * 2);

    // Q fragments: 4 k-steps of 16 over d=64, packed bf16 pairs
    uint32_t qf[4][4];
#pragma unroll
    for (int ks = 0; ks < 4; ks++) {
        int col = ks * 16 + 2 * t;
        qf[ks][0] = *(const uint32_t*)&qbase[(size_t)row_l * HID + col];
        qf[ks][1] = *(const uint32_t*)&qbase[(size_t)(row_l + 8) * HID + col];
        qf[ks][2] = *(const uint32_t*)&qbase[(size_t)row_l * HID + col + 8];
        qf[ks][3] = *(const uint32_t*)&qbase[(size_t)(row_l + 8) * HID + col + 8];
    }

    float o[8][4];
#pragma unroll
    for (int nt = 0; nt < 8; nt++)
#pragma unroll
        for (int c = 0; c < 4; c++) o[nt][c] = 0.f;

    float m0 = -3.0e38f, m1 = -3.0e38f, l0 = 0.f, l1 = 0.f;
    const float scale = 0.04419417382415922f;  // 1/sqrt(512)
    const int n_kt = 2 * qt + 2;

    for (int kt = 0; kt < n_kt; kt++) {
        __syncthreads();
        // load K, V tiles (64 keys x 64 d, bf16): 512 uint4, 2 per thread
#pragma unroll
        for (int i = 0; i < 2; i++) {
            int idx = tid + i * 256;
            int row = idx >> 3;
            int col = (idx & 7) * 8;
            size_t gidx = (size_t)(kt * 64 + row) * HID + col;
            uint4 kv = *(const uint4*)&kbase[gidx];
            uint4 vv = *(const uint4*)&vbase[gidx];
            uint32_t* kd = (uint32_t*)&Ks[row * KP + col];
            kd[0] = kv.x; kd[1] = kv.y; kd[2] = kv.z; kd[3] = kv.w;
            uint32_t* vd = (uint32_t*)&Vs[row * KP + col];
            vd[0] = vv.x; vd[1] = vv.y; vd[2] = vv.z; vd[3] = vv.w;
        }
        if (tid < 64) kms[tid] = g_kmask[b * SEQ + kt * 64 + tid];
        __syncthreads();

        // per-warp causal skip: whole tile above this warp's rows
        if (kt * 64 > wmax) continue;

        // ---- S = Q K^T : per nt, two ldmatrix.x4 cover k=0..63 ----
        float s[8][4];
#pragma unroll
        for (int nt = 0; nt < 8; nt++) {
            s[nt][0] = 0.f; s[nt][1] = 0.f; s[nt][2] = 0.f; s[nt][3] = 0.f;
            uint32_t base = k_addr0 + (uint32_t)(nt * 8 * KP * 2);
            uint32_t b0, b1, b2, b3;
            LDSM_X4(b0, b1, b2, b3, base);          // k 0..31
            {
                uint32_t bf[2] = {b0, b1};
                MMA_BF16(s[nt], qf[0], bf);
                bf[0] = b2; bf[1] = b3;
                MMA_BF16(s[nt], qf[1], bf);
            }
            LDSM_X4(b0, b1, b2, b3, base + 64);     // k 32..63 (+32 u16)
            {
                uint32_t bf[2] = {b0, b1};
                MMA_BF16(s[nt], qf[2], bf);
                bf[0] = b2; bf[1] = b3;
                MMA_BF16(s[nt], qf[3], bf);
            }
        }

        // ---- scale + masks (causal compare only when tile touches diagonal)
        const bool diag = (kt * 64 + 63 > wmin);
#pragma unroll
        for (int nt = 0; nt < 8; nt++) {
            int c0 = nt * 8 + 2 * t;
            float km0 = kms[c0], km1 = kms[c0 + 1];
            int cg0 = kt * 64 + c0;
#pragma unroll
            for (int c = 0; c < 4; c++) {
                int colg = cg0 + (c & 1);
                int rowg = (c < 2) ? row_l : row_l + 8;
                float km = (c & 1) ? km1 : km0;
                float v = s[nt][c] * scale;
                if (km == 0.f || (diag && colg > rowg)) v = NEGV;
                s[nt][c] = v;
            }
        }

        // ---- online softmax on fragments ----
        float rm0 = -3.0e38f, rm1 = -3.0e38f;
#pragma unroll
        for (int nt = 0; nt < 8; nt++) {
            rm0 = fmaxf(rm0, fmaxf(s[nt][0], s[nt][1]));
            rm1 = fmaxf(rm1, fmaxf(s[nt][2], s[nt][3]));
        }
        rm0 = fmaxf(rm0, __shfl_xor_sync(0xFFFFFFFFu, rm0, 1));
        rm0 = fmaxf(rm0, __shfl_xor_sync(0xFFFFFFFFu, rm0, 2));
        rm1 = fmaxf(rm1, __shfl_xor_sync(0xFFFFFFFFu, rm1, 1));
        rm1 = fmaxf(rm1, __shfl_xor_sync(0xFFFFFFFFu, rm1, 2));

        float mn0 = fmaxf(m0, rm0);
        float mn1 = fmaxf(m1, rm1);
        float rs0 = 0.f, rs1 = 0.f;
#pragma unroll
        for (int nt = 0; nt < 8; nt++) {
            s[nt][0] = __expf(s[nt][0] - mn0);
            s[nt][1] = __expf(s[nt][1] - mn0);
            s[nt][2] = __expf(s[nt][2] - mn1);
            s[nt][3] = __expf(s[nt][3] - mn1);
            rs0 += s[nt][0] + s[nt][1];
            rs1 += s[nt][2] + s[nt][3];
        }
        rs0 += __shfl_xor_sync(0xFFFFFFFFu, rs0, 1);
        rs0 += __shfl_xor_sync(0xFFFFFFFFu, rs0, 2);
        rs1 += __shfl_xor_sync(0xFFFFFFFFu, rs1, 1);
        rs1 += __shfl_xor_sync(0xFFFFFFFFu, rs1, 2);

        float sc0 = __expf(m0 - mn0);
        float sc1 = __expf(m1 - mn1);
        l0 = l0 * sc0 + rs0;
        l1 = l1 * sc1 + rs1;
        m0 = mn0; m1 = mn1;
#pragma unroll
        for (int nt = 0; nt < 8; nt++) {
            o[nt][0] *= sc0; o[nt][1] *= sc0;
            o[nt][2] *= sc1; o[nt][3] *= sc1;
        }

        // ---- O += P V : A-frag = repacked S; B-frags via trans ldmatrix.x4
#pragma unroll
        for (int kc = 0; kc < 4; kc++) {
            uint32_t pa[4];
            pa[0] = pack_bf16(s[2 * kc][0],     s[2 * kc][1]);
            pa[1] = pack_bf16(s[2 * kc][2],     s[2 * kc][3]);
            pa[2] = pack_bf16(s[2 * kc + 1][0], s[2 * kc + 1][1]);
            pa[3] = pack_bf16(s[2 * kc + 1][2], s[2 * kc + 1][3]);
            uint32_t kbaseaddr = v_addr0 + (uint32_t)(kc * 16 * KP * 2);
#pragma unroll
            for (int half = 0; half < 4; half++) {   // d pairs (16 d per x4)
                uint32_t b0, b1, b2, b3;
                LDSM_X4_T(b0, b1, b2, b3, kbaseaddr + (uint32_t)(half * 32));
                uint32_t bf[2] = {b0, b1};
                MMA_BF16(o[half * 2], pa, bf);
                bf[0] = b2; bf[1] = b3;
                MMA_BF16(o[half * 2 + 1], pa, bf);
            }
        }
    }

    // ---- epilogue: normalize, query-mask, residual, store ----
    const int grow0 = b * SEQ + row_l;
    const float fac0 = (1.0f / l0) * g_qmask[grow0];
    const float fac1 = (1.0f / l1) * g_qmask[grow0 + 8];
#pragma unroll
    for (int nt2 = 0; nt2 < 8; nt2++) {
        int col = h * DH + nt2 * 8 + 2 * t;
        size_t a0 = (size_t)grow0 * HID + col;
        size_t a1 = (size_t)(grow0 + 8) * HID + col;
        float2 lo = make_float2(o[nt2][0] * fac0 + queries[a0],
                                o[nt2][1] * fac0 + queries[a0 + 1]);
        float2 hi = make_float2(o[nt2][2] * fac1 + queries[a1],
                                o[nt2][3] * fac1 + queries[a1 + 1]);
        *(float2*)&out[a0] = lo;
        *(float2*)&out[a1] = hi;
    }
}

// ---------------- launcher --------------------------------------------------
extern "C" void kernel_launch(void* const* d_in, const int* in_sizes, int n_in,
                              void* d_out, int out_size) {
    const float* queries = (const float*)d_in[0];
    const float* keys    = (const float*)d_in[1];
    const float* Wq      = (const float*)d_in[2];
    const float* bq      = (const float*)d_in[3];
    const float* Wk      = (const float*)d_in[4];
    const float* bk      = (const float*)d_in[5];
    const float* Wv      = (const float*)d_in[6];
    const float* bv      = (const float*)d_in[7];
    float* out = (float*)d_out;

    mask_kernel<<<(2 * ROWS) / 8, 256>>>(queries, keys);

    gemm_qkv<<<dim3(HID / 128, ROWS / 128, 3), 256>>>(queries, keys,
                                                      Wq, bq, Wk, bk, Wv, bv);

    attn_kernel<<<dim3(SEQ / 128, BATCH, NH), 256>>>(queries, out);
}

// round 9
// speedup vs baseline: 1.1393x; 1.1393x over previous
#include <cuda_runtime.h>
#include <cuda_bf16.h>
#include <math.h>
#include <stdint.h>

// Problem constants
#define BATCH 32
#define SEQ   1024
#define HID   512
#define NH    8
#define DH    64                 // head dim = 512/8
#define ROWS  (BATCH*SEQ)        // 32768
#define NEGV  (-4294967295.0f)   // -(2^32)+1, matches reference mask value

// ---------------- scratch (static device globals; no allocations) ----------
__device__ uint16_t g_q[(size_t)ROWS * HID];
__device__ uint16_t g_k[(size_t)ROWS * HID];
__device__ uint16_t g_v[(size_t)ROWS * HID];
__device__ float    g_qmask[ROWS];
__device__ float    g_kmask[ROWS];

__device__ __forceinline__ uint32_t pack_bf16(float lo, float hi) {
    __nv_bfloat162 p = __floats2bfloat162_rn(lo, hi);   // x = lo (low half)
    return *reinterpret_cast<uint32_t*>(&p);
}

#define MMA_BF16(acc, a, b)                                              \
    asm volatile(                                                        \
        "mma.sync.aligned.m16n8k16.row.col.f32.bf16.bf16.f32 "           \
        "{%0,%1,%2,%3}, {%4,%5,%6,%7}, {%8,%9}, {%0,%1,%2,%3};"          \
        : "+f"((acc)[0]), "+f"((acc)[1]), "+f"((acc)[2]), "+f"((acc)[3]) \
        : "r"((a)[0]), "r"((a)[1]), "r"((a)[2]), "r"((a)[3]),            \
          "r"((b)[0]), "r"((b)[1]))

#define LDSM_X4(r0, r1, r2, r3, addr)                                    \
    asm volatile(                                                        \
        "ldmatrix.sync.aligned.m8n8.x4.shared.b16 {%0,%1,%2,%3}, [%4];"  \
        : "=r"(r0), "=r"(r1), "=r"(r2), "=r"(r3) : "r"(addr))

#define LDSM_X4_T(r0, r1, r2, r3, addr)                                  \
    asm volatile(                                                        \
        "ldmatrix.sync.aligned.m8n8.x4.trans.shared.b16 {%0,%1,%2,%3}, [%4];" \
        : "=r"(r0), "=r"(r1), "=r"(r2), "=r"(r3) : "r"(addr))

// ---------------- kernel 1: masks -----------------------------------------
__global__ void mask_kernel(const float* __restrict__ queries,
                            const float* __restrict__ keys) {
    int row  = blockIdx.x * 8 + (threadIdx.x >> 5);   // 0 .. 2*ROWS-1
    int lane = threadIdx.x & 31;
    const float* src;
    float* dst;
    if (row < ROWS) { src = queries + (size_t)row * HID; dst = g_qmask + row; }
    else            { src = keys + (size_t)(row - ROWS) * HID; dst = g_kmask + (row - ROWS); }
    float s = 0.f;
#pragma unroll
    for (int i = 0; i < HID / 32; i++) s += src[lane + i * 32];
#pragma unroll
    for (int off = 16; off > 0; off >>= 1) s += __shfl_xor_sync(0xFFFFFFFFu, s, off);
    if (lane == 0) *dst = (s != 0.0f) ? 1.0f : 0.0f;
}

// ---------------- kernel 2: QKV projection GEMM (bf16 tensor cores) --------
// (unchanged — passing at ~180us)
#define GAP 72     // As pitch (bf16 units)
#define GBP 136    // Bs pitch (bf16 units)

__global__ __launch_bounds__(256, 2)
void gemm_qkv(const float* __restrict__ queries, const float* __restrict__ keys,
              const float* __restrict__ Wq, const float* __restrict__ bq,
              const float* __restrict__ Wk, const float* __restrict__ bk,
              const float* __restrict__ Wv, const float* __restrict__ bv) {
    const float* A; const float* W; const float* bias; uint16_t* C;
    if (blockIdx.z == 0)      { A = queries; W = Wq; bias = bq; C = g_q; }
    else if (blockIdx.z == 1) { A = keys;    W = Wk; bias = bk; C = g_k; }
    else                      { A = keys;    W = Wv; bias = bv; C = g_v; }

    __shared__ uint16_t As[128 * GAP];
    __shared__ uint16_t Bs[64 * GBP];

    const int tid    = threadIdx.x;
    const int wid    = tid >> 5;
    const int lane   = tid & 31;
    const int g      = lane >> 2;
    const int t      = lane & 3;
    const int warp_m = (wid & 1) * 64;
    const int warp_n = (wid >> 1) * 32;
    const int m0     = blockIdx.y * 128;
    const int n0     = blockIdx.x * 128;

    float acc[4][4][4];
#pragma unroll
    for (int mt = 0; mt < 4; mt++)
#pragma unroll
        for (int nt = 0; nt < 4; nt++)
#pragma unroll
            for (int c = 0; c < 4; c++) acc[mt][nt][c] = 0.f;

    for (int k0 = 0; k0 < HID; k0 += 64) {
#pragma unroll
        for (int i = 0; i < 8; i++) {
            int idx = tid + i * 256;
            int row = idx >> 4;
            int col = (idx & 15) * 4;
            float4 v = *(const float4*)&A[(size_t)(m0 + row) * HID + k0 + col];
            uint32_t* d = (uint32_t*)&As[row * GAP + col];
            d[0] = pack_bf16(v.x, v.y);
            d[1] = pack_bf16(v.z, v.w);
        }
#pragma unroll
        for (int i = 0; i < 8; i++) {
            int idx = tid + i * 256;
            int row = idx >> 5;
            int col = (idx & 31) * 4;
            float4 v = *(const float4*)&W[(size_t)(k0 + row) * HID + n0 + col];
            uint32_t* d = (uint32_t*)&Bs[row * GBP + col];
            d[0] = pack_bf16(v.x, v.y);
            d[1] = pack_bf16(v.z, v.w);
        }
        __syncthreads();

#pragma unroll
        for (int ks = 0; ks < 64; ks += 16) {
            uint32_t af[4][4];
#pragma unroll
            for (int mt = 0; mt < 4; mt++) {
                int am = warp_m + mt * 16 + g;
                af[mt][0] = *(uint32_t*)&As[am * GAP + ks + 2 * t];
                af[mt][1] = *(uint32_t*)&As[(am + 8) * GAP + ks + 2 * t];
                af[mt][2] = *(uint32_t*)&As[am * GAP + ks + 8 + 2 * t];
                af[mt][3] = *(uint32_t*)&As[(am + 8) * GAP + ks + 8 + 2 * t];
            }
            uint32_t bf[4][2];
#pragma unroll
            for (int nt = 0; nt < 4; nt++) {
                int bn = warp_n + nt * 8 + g;
                bf[nt][0] = (uint32_t)Bs[(ks + 2 * t) * GBP + bn]
                          | ((uint32_t)Bs[(ks + 2 * t + 1) * GBP + bn] << 16);
                bf[nt][1] = (uint32_t)Bs[(ks + 2 * t + 8) * GBP + bn]
                          | ((uint32_t)Bs[(ks + 2 * t + 9) * GBP + bn] << 16);
            }
#pragma unroll
            for (int mt = 0; mt < 4; mt++)
#pragma unroll
                for (int nt = 0; nt < 4; nt++)
                    MMA_BF16(acc[mt][nt], af[mt], bf[nt]);
        }
        __syncthreads();
    }

#pragma unroll
    for (int mt = 0; mt < 4; mt++) {
        int row0 = m0 + warp_m + mt * 16 + g;
#pragma unroll
        for (int nt = 0; nt < 4; nt++) {
            int col = n0 + warp_n + nt * 8 + t * 2;
            float b0 = bias[col], b1 = bias[col + 1];
            *(uint32_t*)&C[(size_t)row0 * HID + col] =
                pack_bf16(acc[mt][nt][0] + b0, acc[mt][nt][1] + b1);
            *(uint32_t*)&C[(size_t)(row0 + 8) * HID + col] =
                pack_bf16(acc[mt][nt][2] + b0, acc[mt][nt][3] + b1);
        }
    }
}

// ---------------- kernel 3: flash attention (bf16 + swizzled ldmatrix) -----
// grid (16 q-tiles of 64, 32 batch, 8 heads), 128 threads = 4 warps x 16 rows.
// K/V tiles stored XOR-swizzled: 64 rows x 128B; byte offset =
//   row*128 + ((chunk ^ (row&7)) << 4), chunk = d16-chunk (0..7).
// K b-frags: non-trans ldmatrix.x4 (conflict-free); V: trans ldmatrix.x4.
__global__ __launch_bounds__(128)
void attn_kernel(const float* __restrict__ queries, float* __restrict__ out) {
    const int qt = blockIdx.x;   // 0..15
    const int b  = blockIdx.y;   // 0..31
    const int h  = blockIdx.z;   // 0..7

    __shared__ uint16_t Ks[64 * 64];   // swizzled, 8 KB
    __shared__ uint16_t Vs[64 * 64];   // swizzled, 8 KB
    __shared__ float    kms[64];

    const int tid  = threadIdx.x;
    const int w    = tid >> 5;
    const int lane = tid & 31;
    const int g    = lane >> 2;
    const int t    = lane & 3;
    const int r    = lane & 7;         // ldmatrix row-within-matrix

    const size_t headoff = (size_t)b * SEQ * HID + h * DH;
    const uint16_t* qbase = g_q + headoff;
    const uint16_t* kbase = g_k + headoff;
    const uint16_t* vbase = g_v + headoff;

    const int row_l = qt * 64 + w * 16 + g;   // this thread's frag row (local)

    const uint32_t ks_base = (uint32_t)__cvta_generic_to_shared(Ks);
    const uint32_t vs_base = (uint32_t)__cvta_generic_to_shared(Vs);

    // K ldmatrix: matrix q = lane>>3 covers d-chunk q; row = key = nt*8 + r.
    // addr(nt) = ks_base + (nt*8+r)*128 + ((q ^ r) << 4); second x4 = addr ^ 64.
    const uint32_t k_sw = (uint32_t)((((lane >> 3) ^ r) & 7) << 4);
    const uint32_t k_addr0 = ks_base + (uint32_t)(r * 128) + k_sw;

    // V trans ldmatrix: key = kc*16 + ((lane>>3)&1)*8 + r ; d-chunk = (lane>>4) + 2*half.
    const int      v_keyoff = ((lane >> 3) & 1) * 8 + r;
    const uint32_t q2 = (uint32_t)(lane >> 4);

    // Q fragments: 4 k-steps of 16 over d=64, packed bf16 pairs
    uint32_t qf[4][4];
#pragma unroll
    for (int ks = 0; ks < 4; ks++) {
        int col = ks * 16 + 2 * t;
        qf[ks][0] = *(const uint32_t*)&qbase[(size_t)row_l * HID + col];
        qf[ks][1] = *(const uint32_t*)&qbase[(size_t)(row_l + 8) * HID + col];
        qf[ks][2] = *(const uint32_t*)&qbase[(size_t)row_l * HID + col + 8];
        qf[ks][3] = *(const uint32_t*)&qbase[(size_t)(row_l + 8) * HID + col + 8];
    }

    float o[8][4];
#pragma unroll
    for (int nt = 0; nt < 8; nt++)
#pragma unroll
        for (int c = 0; c < 4; c++) o[nt][c] = 0.f;

    float m0 = -3.0e38f, m1 = -3.0e38f, l0 = 0.f, l1 = 0.f;
    const float scale = 0.04419417382415922f;  // 1/sqrt(512)

    for (int kt = 0; kt <= qt; kt++) {
        __syncthreads();
        // load K, V tiles into swizzled smem: 512 16B-chunks each, 4/thread
#pragma unroll
        for (int i = 0; i < 4; i++) {
            int idx = tid + i * 128;
            int row = idx >> 3;
            int c   = idx & 7;
            int swc = c ^ (row & 7);
            size_t gidx = (size_t)(kt * 64 + row) * HID + c * 8;
            *(uint4*)((char*)Ks + row * 128 + swc * 16) = *(const uint4*)&kbase[gidx];
            *(uint4*)((char*)Vs + row * 128 + swc * 16) = *(const uint4*)&vbase[gidx];
        }
        if (tid < 64) kms[tid] = g_kmask[b * SEQ + kt * 64 + tid];
        __syncthreads();

        // ---- S = Q K^T : per nt, two conflict-free ldmatrix.x4 ----
        float s[8][4];
#pragma unroll
        for (int nt = 0; nt < 8; nt++) {
            s[nt][0] = 0.f; s[nt][1] = 0.f; s[nt][2] = 0.f; s[nt][3] = 0.f;
            uint32_t base = k_addr0 + (uint32_t)(nt * 8 * 128);
            uint32_t b0, b1, b2, b3;
            LDSM_X4(b0, b1, b2, b3, base);          // d-chunks (q^r): k 0..31
            {
                uint32_t bf[2] = {b0, b1};
                MMA_BF16(s[nt], qf[0], bf);
                bf[0] = b2; bf[1] = b3;
                MMA_BF16(s[nt], qf[1], bf);
            }
            LDSM_X4(b0, b1, b2, b3, base ^ 64u);    // chunk^4: k 32..63
            {
                uint32_t bf[2] = {b0, b1};
                MMA_BF16(s[nt], qf[2], bf);
                bf[0] = b2; bf[1] = b3;
                MMA_BF16(s[nt], qf[3], bf);
            }
        }

        // ---- scale + masks (causal only on diagonal tile) ----
        const bool diag = (kt == qt);
#pragma unroll
        for (int nt = 0; nt < 8; nt++) {
            int c0 = nt * 8 + 2 * t;
            float km0 = kms[c0], km1 = kms[c0 + 1];
            int cg0 = kt * 64 + c0;
#pragma unroll
            for (int c = 0; c < 4; c++) {
                int colg = cg0 + (c & 1);
                int rowg = (c < 2) ? row_l : row_l + 8;
                float km = (c & 1) ? km1 : km0;
                float v = s[nt][c] * scale;
                if (km == 0.f || (diag && colg > rowg)) v = NEGV;
                s[nt][c] = v;
            }
        }

        // ---- online softmax on fragments ----
        float rm0 = -3.0e38f, rm1 = -3.0e38f;
#pragma unroll
        for (int nt = 0; nt < 8; nt++) {
            rm0 = fmaxf(rm0, fmaxf(s[nt][0], s[nt][1]));
            rm1 = fmaxf(rm1, fmaxf(s[nt][2], s[nt][3]));
        }
        rm0 = fmaxf(rm0, __shfl_xor_sync(0xFFFFFFFFu, rm0, 1));
        rm0 = fmaxf(rm0, __shfl_xor_sync(0xFFFFFFFFu, rm0, 2));
        rm1 = fmaxf(rm1, __shfl_xor_sync(0xFFFFFFFFu, rm1, 1));
        rm1 = fmaxf(rm1, __shfl_xor_sync(0xFFFFFFFFu, rm1, 2));

        float mn0 = fmaxf(m0, rm0);
        float mn1 = fmaxf(m1, rm1);
        float rs0 = 0.f, rs1 = 0.f;
#pragma unroll
        for (int nt = 0; nt < 8; nt++) {
            s[nt][0] = __expf(s[nt][0] - mn0);
            s[nt][1] = __expf(s[nt][1] - mn0);
            s[nt][2] = __expf(s[nt][2] - mn1);
            s[nt][3] = __expf(s[nt][3] - mn1);
            rs0 += s[nt][0] + s[nt][1];
            rs1 += s[nt][2] + s[nt][3];
        }
        rs0 += __shfl_xor_sync(0xFFFFFFFFu, rs0, 1);
        rs0 += __shfl_xor_sync(0xFFFFFFFFu, rs0, 2);
        rs1 += __shfl_xor_sync(0xFFFFFFFFu, rs1, 1);
        rs1 += __shfl_xor_sync(0xFFFFFFFFu, rs1, 2);

        float sc0 = __expf(m0 - mn0);
        float sc1 = __expf(m1 - mn1);
        l0 = l0 * sc0 + rs0;
        l1 = l1 * sc1 + rs1;
        m0 = mn0; m1 = mn1;
#pragma unroll
        for (int nt = 0; nt < 8; nt++) {
            o[nt][0] *= sc0; o[nt][1] *= sc0;
            o[nt][2] *= sc1; o[nt][3] *= sc1;
        }

        // ---- O += P V : A-frag = repacked S; B via trans ldmatrix.x4 ------
#pragma unroll
        for (int kc = 0; kc < 4; kc++) {
            uint32_t pa[4];
            pa[0] = pack_bf16(s[2 * kc][0],     s[2 * kc][1]);
            pa[1] = pack_bf16(s[2 * kc][2],     s[2 * kc][3]);
            pa[2] = pack_bf16(s[2 * kc + 1][0], s[2 * kc + 1][1]);
            pa[3] = pack_bf16(s[2 * kc + 1][2], s[2 * kc + 1][3]);
            uint32_t vrow = vs_base + (uint32_t)((kc * 16 + v_keyoff) * 128);
#pragma unroll
            for (int half = 0; half < 4; half++) {   // d-chunk = 2*half + q2
                uint32_t addr = vrow +
                    (uint32_t)(((((uint32_t)(half << 1) | q2) ^ (uint32_t)r) & 7u) << 4);
                uint32_t b0, b1, b2, b3;
                LDSM_X4_T(b0, b1, b2, b3, addr);
                uint32_t bf[2] = {b0, b1};
                MMA_BF16(o[half * 2], pa, bf);
                bf[0] = b2; bf[1] = b3;
                MMA_BF16(o[half * 2 + 1], pa, bf);
            }
        }
    }

    // ---- epilogue: normalize, query-mask, residual, store ----
    const int grow0 = b * SEQ + row_l;
    const float fac0 = (1.0f / l0) * g_qmask[grow0];
    const float fac1 = (1.0f / l1) * g_qmask[grow0 + 8];
#pragma unroll
    for (int nt2 = 0; nt2 < 8; nt2++) {
        int col = h * DH + nt2 * 8 + 2 * t;
        size_t a0 = (size_t)grow0 * HID + col;
        size_t a1 = (size_t)(grow0 + 8) * HID + col;
        float2 lo = make_float2(o[nt2][0] * fac0 + queries[a0],
                                o[nt2][1] * fac0 + queries[a0 + 1]);
        float2 hi = make_float2(o[nt2][2] * fac1 + queries[a1],
                                o[nt2][3] * fac1 + queries[a1 + 1]);
        *(float2*)&out[a0] = lo;
        *(float2*)&out[a1] = hi;
    }
}

// ---------------- launcher --------------------------------------------------
extern "C" void kernel_launch(void* const* d_in, const int* in_sizes, int n_in,
                              void* d_out, int out_size) {
    const float* queries = (const float*)d_in[0];
    const float* keys    = (const float*)d_in[1];
    const float* Wq      = (const float*)d_in[2];
    const float* bq      = (const float*)d_in[3];
    const float* Wk      = (const float*)d_in[4];
    const float* bk      = (const float*)d_in[5];
    const float* Wv      = (const float*)d_in[6];
    const float* bv      = (const float*)d_in[7];
    float* out = (float*)d_out;

    mask_kernel<<<(2 * ROWS) / 8, 256>>>(queries, keys);

    gemm_qkv<<<dim3(HID / 128, ROWS / 128, 3), 256>>>(queries, keys,
                                                      Wq, bq, Wk, bk, Wv, bv);

    attn_kernel<<<dim3(SEQ / 64, BATCH, NH), 128>>>(queries, out);
}

// round 11
// speedup vs baseline: 1.2129x; 1.0646x over previous
#include <cuda_runtime.h>
#include <cuda_bf16.h>
#include <math.h>
#include <stdint.h>

// Problem constants
#define BATCH 32
#define SEQ   1024
#define HID   512
#define NH    8
#define DH    64                 // head dim = 512/8
#define ROWS  (BATCH*SEQ)        // 32768
#define NEGV  (-4294967295.0f)   // -(2^32)+1, matches reference mask value

// ---------------- scratch (static device globals; no allocations) ----------
__device__ uint16_t g_q[(size_t)ROWS * HID];
__device__ uint16_t g_k[(size_t)ROWS * HID];
__device__ uint16_t g_v[(size_t)ROWS * HID];
__device__ float    g_qmask[ROWS];
__device__ float    g_kmask[ROWS];

__device__ __forceinline__ uint32_t pack_bf16(float lo, float hi) {
    __nv_bfloat162 p = __floats2bfloat162_rn(lo, hi);   // x = lo (low half)
    return *reinterpret_cast<uint32_t*>(&p);
}

#define MMA_BF16(acc, a, b)                                              \
    asm volatile(                                                        \
        "mma.sync.aligned.m16n8k16.row.col.f32.bf16.bf16.f32 "           \
        "{%0,%1,%2,%3}, {%4,%5,%6,%7}, {%8,%9}, {%0,%1,%2,%3};"          \
        : "+f"((acc)[0]), "+f"((acc)[1]), "+f"((acc)[2]), "+f"((acc)[3]) \
        : "r"((a)[0]), "r"((a)[1]), "r"((a)[2]), "r"((a)[3]),            \
          "r"((b)[0]), "r"((b)[1]))

#define LDSM_X4(r0, r1, r2, r3, addr)                                    \
    asm volatile(                                                        \
        "ldmatrix.sync.aligned.m8n8.x4.shared.b16 {%0,%1,%2,%3}, [%4];"  \
        : "=r"(r0), "=r"(r1), "=r"(r2), "=r"(r3) : "r"(addr))

#define LDSM_X4_T(r0, r1, r2, r3, addr)                                  \
    asm volatile(                                                        \
        "ldmatrix.sync.aligned.m8n8.x4.trans.shared.b16 {%0,%1,%2,%3}, [%4];" \
        : "=r"(r0), "=r"(r1), "=r"(r2), "=r"(r3) : "r"(addr))

#define CP_ASYNC_16(dst, src)                                            \
    asm volatile("cp.async.cg.shared.global [%0], [%1], 16;"             \
                 :: "r"(dst), "l"(src))
#define CP_COMMIT()  asm volatile("cp.async.commit_group;" ::: "memory")
#define CP_WAIT_ALL() asm volatile("cp.async.wait_group 0;" ::: "memory")

// ---------------- kernel 1: masks -----------------------------------------
__global__ void mask_kernel(const float* __restrict__ queries,
                            const float* __restrict__ keys) {
    int row  = blockIdx.x * 8 + (threadIdx.x >> 5);   // 0 .. 2*ROWS-1
    int lane = threadIdx.x & 31;
    const float* src;
    float* dst;
    if (row < ROWS) { src = queries + (size_t)row * HID; dst = g_qmask + row; }
    else            { src = keys + (size_t)(row - ROWS) * HID; dst = g_kmask + (row - ROWS); }
    float s = 0.f;
#pragma unroll
    for (int i = 0; i < HID / 32; i++) s += src[lane + i * 32];
#pragma unroll
    for (int off = 16; off > 0; off >>= 1) s += __shfl_xor_sync(0xFFFFFFFFu, s, off);
    if (lane == 0) *dst = (s != 0.0f) ? 1.0f : 0.0f;
}

// ---------------- kernel 2: QKV projection GEMM (bf16 tensor cores) --------
// (unchanged — passing)
#define GAP 72     // As pitch (bf16 units)
#define GBP 136    // Bs pitch (bf16 units)

__global__ __launch_bounds__(256, 2)
void gemm_qkv(const float* __restrict__ queries, const float* __restrict__ keys,
              const float* __restrict__ Wq, const float* __restrict__ bq,
              const float* __restrict__ Wk, const float* __restrict__ bk,
              const float* __restrict__ Wv, const float* __restrict__ bv) {
    const float* A; const float* W; const float* bias; uint16_t* C;
    if (blockIdx.z == 0)      { A = queries; W = Wq; bias = bq; C = g_q; }
    else if (blockIdx.z == 1) { A = keys;    W = Wk; bias = bk; C = g_k; }
    else                      { A = keys;    W = Wv; bias = bv; C = g_v; }

    __shared__ uint16_t As[128 * GAP];
    __shared__ uint16_t Bs[64 * GBP];

    const int tid    = threadIdx.x;
    const int wid    = tid >> 5;
    const int lane   = tid & 31;
    const int g      = lane >> 2;
    const int t      = lane & 3;
    const int warp_m = (wid & 1) * 64;
    const int warp_n = (wid >> 1) * 32;
    const int m0     = blockIdx.y * 128;
    const int n0     = blockIdx.x * 128;

    float acc[4][4][4];
#pragma unroll
    for (int mt = 0; mt < 4; mt++)
#pragma unroll
        for (int nt = 0; nt < 4; nt++)
#pragma unroll
            for (int c = 0; c < 4; c++) acc[mt][nt][c] = 0.f;

    for (int k0 = 0; k0 < HID; k0 += 64) {
#pragma unroll
        for (int i = 0; i < 8; i++) {
            int idx = tid + i * 256;
            int row = idx >> 4;
            int col = (idx & 15) * 4;
            float4 v = *(const float4*)&A[(size_t)(m0 + row) * HID + k0 + col];
            uint32_t* d = (uint32_t*)&As[row * GAP + col];
            d[0] = pack_bf16(v.x, v.y);
            d[1] = pack_bf16(v.z, v.w);
        }
#pragma unroll
        for (int i = 0; i < 8; i++) {
            int idx = tid + i * 256;
            int row = idx >> 5;
            int col = (idx & 31) * 4;
            float4 v = *(const float4*)&W[(size_t)(k0 + row) * HID + n0 + col];
            uint32_t* d = (uint32_t*)&Bs[row * GBP + col];
            d[0] = pack_bf16(v.x, v.y);
            d[1] = pack_bf16(v.z, v.w);
        }
        __syncthreads();

#pragma unroll
        for (int ks = 0; ks < 64; ks += 16) {
            uint32_t af[4][4];
#pragma unroll
            for (int mt = 0; mt < 4; mt++) {
                int am = warp_m + mt * 16 + g;
                af[mt][0] = *(uint32_t*)&As[am * GAP + ks + 2 * t];
                af[mt][1] = *(uint32_t*)&As[(am + 8) * GAP + ks + 2 * t];
                af[mt][2] = *(uint32_t*)&As[am * GAP + ks + 8 + 2 * t];
                af[mt][3] = *(uint32_t*)&As[(am + 8) * GAP + ks + 8 + 2 * t];
            }
            uint32_t bf[4][2];
#pragma unroll
            for (int nt = 0; nt < 4; nt++) {
                int bn = warp_n + nt * 8 + g;
                bf[nt][0] = (uint32_t)Bs[(ks + 2 * t) * GBP + bn]
                          | ((uint32_t)Bs[(ks + 2 * t + 1) * GBP + bn] << 16);
                bf[nt][1] = (uint32_t)Bs[(ks + 2 * t + 8) * GBP + bn]
                          | ((uint32_t)Bs[(ks + 2 * t + 9) * GBP + bn] << 16);
            }
#pragma unroll
            for (int mt = 0; mt < 4; mt++)
#pragma unroll
                for (int nt = 0; nt < 4; nt++)
                    MMA_BF16(acc[mt][nt], af[mt], bf[nt]);
        }
        __syncthreads();
    }

#pragma unroll
    for (int mt = 0; mt < 4; mt++) {
        int row0 = m0 + warp_m + mt * 16 + g;
#pragma unroll
        for (int nt = 0; nt < 4; nt++) {
            int col = n0 + warp_n + nt * 8 + t * 2;
            float b0 = bias[col], b1 = bias[col + 1];
            *(uint32_t*)&C[(size_t)row0 * HID + col] =
                pack_bf16(acc[mt][nt][0] + b0, acc[mt][nt][1] + b1);
            *(uint32_t*)&C[(size_t)(row0 + 8) * HID + col] =
                pack_bf16(acc[mt][nt][2] + b0, acc[mt][nt][3] + b1);
        }
    }
}

// ---------------- kernel 3: flash attention (bf16, swizzled, cp.async) -----
// grid (16 q-tiles of 64, 32 batch, 8 heads), 128 threads = 4 warps x 16 rows.
// Double-buffered K/V tiles via cp.async; one __syncthreads per tile.
// Swizzle: byte offset = row*128 + ((chunk ^ (row&7)) << 4).
__global__ __launch_bounds__(128)
void attn_kernel(const float* __restrict__ queries, float* __restrict__ out) {
    const int qt = blockIdx.x;   // 0..15
    const int b  = blockIdx.y;   // 0..31
    const int h  = blockIdx.z;   // 0..7

    __shared__ uint16_t Ks[2][64 * 64];   // swizzled, 8 KB per stage
    __shared__ uint16_t Vs[2][64 * 64];   // swizzled, 8 KB per stage
    __shared__ float    kms[2][64];

    const int tid  = threadIdx.x;
    const int w    = tid >> 5;
    const int lane = tid & 31;
    const int g    = lane >> 2;
    const int t    = lane & 3;
    const int r    = lane & 7;         // ldmatrix row-within-matrix

    const size_t headoff = (size_t)b * SEQ * HID + h * DH;
    const uint16_t* qbase = g_q + headoff;
    const uint16_t* kbase = g_k + headoff;
    const uint16_t* vbase = g_v + headoff;
    const float*    kmrow = g_kmask + b * SEQ;

    const int row_l = qt * 64 + w * 16 + g;   // this thread's frag row (local)

    const uint32_t ks_base  = (uint32_t)__cvta_generic_to_shared(&Ks[0][0]);
    const uint32_t vs_base  = (uint32_t)__cvta_generic_to_shared(&Vs[0][0]);
    const uint32_t kms_base = (uint32_t)__cvta_generic_to_shared(&kms[0][0]);

    // Fixed per-thread pieces of ldmatrix addressing
    const uint32_t k_sw = (uint32_t)((((lane >> 3) ^ r) & 7) << 4);
    const uint32_t k_addr0 = ks_base + (uint32_t)(r * 128) + k_sw;
    const int      v_keyoff = ((lane >> 3) & 1) * 8 + r;
    const uint32_t q2 = (uint32_t)(lane >> 4);

    // Per-thread cp.async slots: 4 x 16B chunks each for K and V
    int ld_row[4], ld_soff[4];
#pragma unroll
    for (int i = 0; i < 4; i++) {
        int idx = tid + i * 128;
        int row = idx >> 3;
        int c   = idx & 7;
        int swc = c ^ (row & 7);
        ld_row[i]  = row;
        ld_soff[i] = row * 128 + swc * 16;
    }

    // Q fragments: 4 k-steps of 16 over d=64, packed bf16 pairs
    uint32_t qf[4][4];
#pragma unroll
    for (int ks = 0; ks < 4; ks++) {
        int col = ks * 16 + 2 * t;
        qf[ks][0] = *(const uint32_t*)&qbase[(size_t)row_l * HID + col];
        qf[ks][1] = *(const uint32_t*)&qbase[(size_t)(row_l + 8) * HID + col];
        qf[ks][2] = *(const uint32_t*)&qbase[(size_t)row_l * HID + col + 8];
        qf[ks][3] = *(const uint32_t*)&qbase[(size_t)(row_l + 8) * HID + col + 8];
    }

    float o[8][4];
#pragma unroll
    for (int nt = 0; nt < 8; nt++)
#pragma unroll
        for (int c = 0; c < 4; c++) o[nt][c] = 0.f;

    float m0 = -3.0e38f, m1 = -3.0e38f, l0 = 0.f, l1 = 0.f;
    const float scale = 0.04419417382415922f;  // 1/sqrt(512)

    // ---- prologue: issue tile 0 into stage 0 ----
    {
#pragma unroll
        for (int i = 0; i < 4; i++) {
            size_t gofs = (size_t)(0 * 64 + ld_row[i]) * HID + (ld_soff[i] == 0 ? 0 : 0);
            // recompute column from slot (c*8 u16): c = (tid + i*128) & 7
            int c = (tid + i * 128) & 7;
            gofs = (size_t)ld_row[i] * HID + c * 8;
            CP_ASYNC_16(ks_base + (uint32_t)ld_soff[i], kbase + gofs);
            CP_ASYNC_16(vs_base + (uint32_t)ld_soff[i], vbase + gofs);
        }
        if (tid < 16) CP_ASYNC_16(kms_base + (uint32_t)(tid * 16), kmrow + tid * 4);
        CP_COMMIT();
    }

    for (int kt = 0; kt <= qt; kt++) {
        const int bfi = kt & 1;
        const uint32_t kofs = (uint32_t)(bfi * 8192);   // stage byte offset

        CP_WAIT_ALL();
        __syncthreads();

        // issue prefetch of tile kt+1 into the other stage
        if (kt < qt) {
            const uint32_t pofs = (uint32_t)((bfi ^ 1) * 8192);
#pragma unroll
            for (int i = 0; i < 4; i++) {
                int c = (tid + i * 128) & 7;
                size_t gofs = (size_t)((kt + 1) * 64 + ld_row[i]) * HID + c * 8;
                CP_ASYNC_16(ks_base + pofs + (uint32_t)ld_soff[i], kbase + gofs);
                CP_ASYNC_16(vs_base + pofs + (uint32_t)ld_soff[i], vbase + gofs);
            }
            if (tid < 16)
                CP_ASYNC_16(kms_base + (uint32_t)((bfi ^ 1) * 256 + tid * 16),
                            kmrow + (kt + 1) * 64 + tid * 4);
            CP_COMMIT();
        }

        // ---- S = Q K^T : per nt, two conflict-free ldmatrix.x4 ----
        float s[8][4];
#pragma unroll
        for (int nt = 0; nt < 8; nt++) {
            s[nt][0] = 0.f; s[nt][1] = 0.f; s[nt][2] = 0.f; s[nt][3] = 0.f;
            uint32_t base = k_addr0 + kofs + (uint32_t)(nt * 8 * 128);
            uint32_t b0, b1, b2, b3;
            LDSM_X4(b0, b1, b2, b3, base);          // k 0..31
            {
                uint32_t bf[2] = {b0, b1};
                MMA_BF16(s[nt], qf[0], bf);
                bf[0] = b2; bf[1] = b3;
                MMA_BF16(s[nt], qf[1], bf);
            }
            LDSM_X4(b0, b1, b2, b3, base ^ 64u);    // k 32..63
            {
                uint32_t bf[2] = {b0, b1};
                MMA_BF16(s[nt], qf[2], bf);
                bf[0] = b2; bf[1] = b3;
                MMA_BF16(s[nt], qf[3], bf);
            }
        }

        // ---- scale + masks (causal only on diagonal tile) ----
        const bool diag = (kt == qt);
#pragma unroll
        for (int nt = 0; nt < 8; nt++) {
            int c0 = nt * 8 + 2 * t;
            float km0 = kms[bfi][c0], km1 = kms[bfi][c0 + 1];
            int cg0 = kt * 64 + c0;
#pragma unroll
            for (int c = 0; c < 4; c++) {
                int colg = cg0 + (c & 1);
                int rowg = (c < 2) ? row_l : row_l + 8;
                float km = (c & 1) ? km1 : km0;
                float v = s[nt][c] * scale;
                if (km == 0.f || (diag && colg > rowg)) v = NEGV;
                s[nt][c] = v;
            }
        }

        // ---- online softmax on fragments ----
        float rm0 = -3.0e38f, rm1 = -3.0e38f;
#pragma unroll
        for (int nt = 0; nt < 8; nt++) {
            rm0 = fmaxf(rm0, fmaxf(s[nt][0], s[nt][1]));
            rm1 = fmaxf(rm1, fmaxf(s[nt][2], s[nt][3]));
        }
        rm0 = fmaxf(rm0, __shfl_xor_sync(0xFFFFFFFFu, rm0, 1));
        rm0 = fmaxf(rm0, __shfl_xor_sync(0xFFFFFFFFu, rm0, 2));
        rm1 = fmaxf(rm1, __shfl_xor_sync(0xFFFFFFFFu, rm1, 1));
        rm1 = fmaxf(rm1, __shfl_xor_sync(0xFFFFFFFFu, rm1, 2));

        float mn0 = fmaxf(m0, rm0);
        float mn1 = fmaxf(m1, rm1);
        float rs0 = 0.f, rs1 = 0.f;
#pragma unroll
        for (int nt = 0; nt < 8; nt++) {
            s[nt][0] = __expf(s[nt][0] - mn0);
            s[nt][1] = __expf(s[nt][1] - mn0);
            s[nt][2] = __expf(s[nt][2] - mn1);
            s[nt][3] = __expf(s[nt][3] - mn1);
            rs0 += s[nt][0] + s[nt][1];
            rs1 += s[nt][2] + s[nt][3];
        }
        rs0 += __shfl_xor_sync(0xFFFFFFFFu, rs0, 1);
        rs0 += __shfl_xor_sync(0xFFFFFFFFu, rs0, 2);
        rs1 += __shfl_xor_sync(0xFFFFFFFFu, rs1, 1);
        rs1 += __shfl_xor_sync(0xFFFFFFFFu, rs1, 2);

        float sc0 = __expf(m0 - mn0);
        float sc1 = __expf(m1 - mn1);
        l0 = l0 * sc0 + rs0;
        l1 = l1 * sc1 + rs1;
        m0 = mn0; m1 = mn1;
#pragma unroll
        for (int nt = 0; nt < 8; nt++) {
            o[nt][0] *= sc0; o[nt][1] *= sc0;
            o[nt][2] *= sc1; o[nt][3] *= sc1;
        }

        // ---- O += P V : A-frag = repacked S; B via trans ldmatrix.x4 ------
#pragma unroll
        for (int kc = 0; kc < 4; kc++) {
            uint32_t pa[4];
            pa[0] = pack_bf16(s[2 * kc][0],     s[2 * kc][1]);
            pa[1] = pack_bf16(s[2 * kc][2],     s[2 * kc][3]);
            pa[2] = pack_bf16(s[2 * kc + 1][0], s[2 * kc + 1][1]);
            pa[3] = pack_bf16(s[2 * kc + 1][2], s[2 * kc + 1][3]);
            uint32_t vrow = vs_base + kofs + (uint32_t)((kc * 16 + v_keyoff) * 128);
#pragma unroll
            for (int half = 0; half < 4; half++) {   // d-chunk = 2*half + q2
                uint32_t addr = vrow +
                    (uint32_t)(((((uint32_t)(half << 1) | q2) ^ (uint32_t)r) & 7u) << 4);
                uint32_t b0, b1, b2, b3;
                LDSM_X4_T(b0, b1, b2, b3, addr);
                uint32_t bf[2] = {b0, b1};
                MMA_BF16(o[half * 2], pa, bf);
                bf[0] = b2; bf[1] = b3;
                MMA_BF16(o[half * 2 + 1], pa, bf);
            }
        }
    }

    // ---- epilogue: normalize, query-mask, residual, store ----
    const int grow0 = b * SEQ + row_l;
    const float fac0 = (1.0f / l0) * g_qmask[grow0];
    const float fac1 = (1.0f / l1) * g_qmask[grow0 + 8];
#pragma unroll
    for (int nt2 = 0; nt2 < 8; nt2++) {
        int col = h * DH + nt2 * 8 + 2 * t;
        size_t a0 = (size_t)grow0 * HID + col;
        size_t a1 = (size_t)(grow0 + 8) * HID + col;
        float2 lo = make_float2(o[nt2][0] * fac0 + queries[a0],
                                o[nt2][1] * fac0 + queries[a0 + 1]);
        float2 hi = make_float2(o[nt2][2] * fac1 + queries[a1],
                                o[nt2][3] * fac1 + queries[a1 + 1]);
        *(float2*)&out[a0] = lo;
        *(float2*)&out[a1] = hi;
    }
}

// ---------------- launcher --------------------------------------------------
extern "C" void kernel_launch(void* const* d_in, const int* in_sizes, int n_in,
                              void* d_out, int out_size) {
    const float* queries = (const float*)d_in[0];
    const float* keys    = (const float*)d_in[1];
    const float* Wq      = (const float*)d_in[2];
    const float* bq      = (const float*)d_in[3];
    const float* Wk      = (const float*)d_in[4];
    const float* bk      = (const float*)d_in[5];
    const float* Wv      = (const float*)d_in[6];
    const float* bv      = (const float*)d_in[7];
    float* out = (float*)d_out;

    mask_kernel<<<(2 * ROWS) / 8, 256>>>(queries, keys);

    gemm_qkv<<<dim3(HID / 128, ROWS / 128, 3), 256>>>(queries, keys,
                                                      Wq, bq, Wk, bk, Wv, bv);

    attn_kernel<<<dim3(SEQ / 64, BATCH, NH), 128>>>(queries, out);
}

// round 12
// speedup vs baseline: 1.2177x; 1.0040x over previous
#include <cuda_runtime.h>
#include <cuda_bf16.h>
#include <math.h>
#include <stdint.h>

// Problem constants
#define BATCH 32
#define SEQ   1024
#define HID   512
#define NH    8
#define DH    64                 // head dim = 512/8
#define ROWS  (BATCH*SEQ)        // 32768
#define NEGV  (-4294967295.0f)   // -(2^32)+1, matches reference mask value

// ---------------- scratch (static device globals; no allocations) ----------
__device__ uint16_t g_q[(size_t)ROWS * HID];
__device__ uint16_t g_k[(size_t)ROWS * HID];
__device__ uint16_t g_v[(size_t)ROWS * HID];
__device__ float    g_qmask[ROWS];
__device__ float    g_kmask[ROWS];

__device__ __forceinline__ uint32_t pack_bf16(float lo, float hi) {
    __nv_bfloat162 p = __floats2bfloat162_rn(lo, hi);   // x = lo (low half)
    return *reinterpret_cast<uint32_t*>(&p);
}

#define MMA_BF16(acc, a, b)                                              \
    asm volatile(                                                        \
        "mma.sync.aligned.m16n8k16.row.col.f32.bf16.bf16.f32 "           \
        "{%0,%1,%2,%3}, {%4,%5,%6,%7}, {%8,%9}, {%0,%1,%2,%3};"          \
        : "+f"((acc)[0]), "+f"((acc)[1]), "+f"((acc)[2]), "+f"((acc)[3]) \
        : "r"((a)[0]), "r"((a)[1]), "r"((a)[2]), "r"((a)[3]),            \
          "r"((b)[0]), "r"((b)[1]))

#define LDSM_X4(r0, r1, r2, r3, addr)                                    \
    asm volatile(                                                        \
        "ldmatrix.sync.aligned.m8n8.x4.shared.b16 {%0,%1,%2,%3}, [%4];"  \
        : "=r"(r0), "=r"(r1), "=r"(r2), "=r"(r3) : "r"(addr))

#define LDSM_X4_T(r0, r1, r2, r3, addr)                                  \
    asm volatile(                                                        \
        "ldmatrix.sync.aligned.m8n8.x4.trans.shared.b16 {%0,%1,%2,%3}, [%4];" \
        : "=r"(r0), "=r"(r1), "=r"(r2), "=r"(r3) : "r"(addr))

#define CP_ASYNC_16(dst, src)                                            \
    asm volatile("cp.async.cg.shared.global [%0], [%1], 16;"             \
                 :: "r"(dst), "l"(src))
#define CP_COMMIT()  asm volatile("cp.async.commit_group;" ::: "memory")
#define CP_WAIT_ALL() asm volatile("cp.async.wait_group 0;" ::: "memory")

// ---------------- kernel 1: masks -----------------------------------------
__global__ void mask_kernel(const float* __restrict__ queries,
                            const float* __restrict__ keys) {
    int row  = blockIdx.x * 8 + (threadIdx.x >> 5);   // 0 .. 2*ROWS-1
    int lane = threadIdx.x & 31;
    const float* src;
    float* dst;
    if (row < ROWS) { src = queries + (size_t)row * HID; dst = g_qmask + row; }
    else            { src = keys + (size_t)(row - ROWS) * HID; dst = g_kmask + (row - ROWS); }
    float s = 0.f;
#pragma unroll
    for (int i = 0; i < HID / 32; i++) s += src[lane + i * 32];
#pragma unroll
    for (int off = 16; off > 0; off >>= 1) s += __shfl_xor_sync(0xFFFFFFFFu, s, off);
    if (lane == 0) *dst = (s != 0.0f) ? 1.0f : 0.0f;
}

// ---------------- kernel 2: QKV projection GEMM (bf16 tensor cores) --------
// (unchanged — passing)
#define GAP 72     // As pitch (bf16 units)
#define GBP 136    // Bs pitch (bf16 units)

__global__ __launch_bounds__(256, 2)
void gemm_qkv(const float* __restrict__ queries, const float* __restrict__ keys,
              const float* __restrict__ Wq, const float* __restrict__ bq,
              const float* __restrict__ Wk, const float* __restrict__ bk,
              const float* __restrict__ Wv, const float* __restrict__ bv) {
    const float* A; const float* W; const float* bias; uint16_t* C;
    if (blockIdx.z == 0)      { A = queries; W = Wq; bias = bq; C = g_q; }
    else if (blockIdx.z == 1) { A = keys;    W = Wk; bias = bk; C = g_k; }
    else                      { A = keys;    W = Wv; bias = bv; C = g_v; }

    __shared__ uint16_t As[128 * GAP];
    __shared__ uint16_t Bs[64 * GBP];

    const int tid    = threadIdx.x;
    const int wid    = tid >> 5;
    const int lane   = tid & 31;
    const int g      = lane >> 2;
    const int t      = lane & 3;
    const int warp_m = (wid & 1) * 64;
    const int warp_n = (wid >> 1) * 32;
    const int m0     = blockIdx.y * 128;
    const int n0     = blockIdx.x * 128;

    float acc[4][4][4];
#pragma unroll
    for (int mt = 0; mt < 4; mt++)
#pragma unroll
        for (int nt = 0; nt < 4; nt++)
#pragma unroll
            for (int c = 0; c < 4; c++) acc[mt][nt][c] = 0.f;

    for (int k0 = 0; k0 < HID; k0 += 64) {
#pragma unroll
        for (int i = 0; i < 8; i++) {
            int idx = tid + i * 256;
            int row = idx >> 4;
            int col = (idx & 15) * 4;
            float4 v = *(const float4*)&A[(size_t)(m0 + row) * HID + k0 + col];
            uint32_t* d = (uint32_t*)&As[row * GAP + col];
            d[0] = pack_bf16(v.x, v.y);
            d[1] = pack_bf16(v.z, v.w);
        }
#pragma unroll
        for (int i = 0; i < 8; i++) {
            int idx = tid + i * 256;
            int row = idx >> 5;
            int col = (idx & 31) * 4;
            float4 v = *(const float4*)&W[(size_t)(k0 + row) * HID + n0 + col];
            uint32_t* d = (uint32_t*)&Bs[row * GBP + col];
            d[0] = pack_bf16(v.x, v.y);
            d[1] = pack_bf16(v.z, v.w);
        }
        __syncthreads();

#pragma unroll
        for (int ks = 0; ks < 64; ks += 16) {
            uint32_t af[4][4];
#pragma unroll
            for (int mt = 0; mt < 4; mt++) {
                int am = warp_m + mt * 16 + g;
                af[mt][0] = *(uint32_t*)&As[am * GAP + ks + 2 * t];
                af[mt][1] = *(uint32_t*)&As[(am + 8) * GAP + ks + 2 * t];
                af[mt][2] = *(uint32_t*)&As[am * GAP + ks + 8 + 2 * t];
                af[mt][3] = *(uint32_t*)&As[(am + 8) * GAP + ks + 8 + 2 * t];
            }
            uint32_t bf[4][2];
#pragma unroll
            for (int nt = 0; nt < 4; nt++) {
                int bn = warp_n + nt * 8 + g;
                bf[nt][0] = (uint32_t)Bs[(ks + 2 * t) * GBP + bn]
                          | ((uint32_t)Bs[(ks + 2 * t + 1) * GBP + bn] << 16);
                bf[nt][1] = (uint32_t)Bs[(ks + 2 * t + 8) * GBP + bn]
                          | ((uint32_t)Bs[(ks + 2 * t + 9) * GBP + bn] << 16);
            }
#pragma unroll
            for (int mt = 0; mt < 4; mt++)
#pragma unroll
                for (int nt = 0; nt < 4; nt++)
                    MMA_BF16(acc[mt][nt], af[mt], bf[nt]);
        }
        __syncthreads();
    }

#pragma unroll
    for (int mt = 0; mt < 4; mt++) {
        int row0 = m0 + warp_m + mt * 16 + g;
#pragma unroll
        for (int nt = 0; nt < 4; nt++) {
            int col = n0 + warp_n + nt * 8 + t * 2;
            float b0 = bias[col], b1 = bias[col + 1];
            *(uint32_t*)&C[(size_t)row0 * HID + col] =
                pack_bf16(acc[mt][nt][0] + b0, acc[mt][nt][1] + b1);
            *(uint32_t*)&C[(size_t)(row0 + 8) * HID + col] =
                pack_bf16(acc[mt][nt][2] + b0, acc[mt][nt][3] + b1);
        }
    }
}

// ---------------- kernel 3: flash attention (bf16, swizzled, cp.async) -----
// grid (16 q-tiles of 64, 32 batch, 8 heads), 128 threads = 4 warps x 16 rows.
// Double-buffered K/V tiles via cp.async; one __syncthreads per tile.
// Swizzle: byte offset = row*128 + ((chunk ^ (row&7)) << 4).
__global__ __launch_bounds__(128)
void attn_kernel(const float* __restrict__ queries, float* __restrict__ out) {
    const int qt = blockIdx.x;   // 0..15
    const int b  = blockIdx.y;   // 0..31
    const int h  = blockIdx.z;   // 0..7

    __shared__ uint16_t Ks[2][64 * 64];   // swizzled, 8 KB per stage
    __shared__ uint16_t Vs[2][64 * 64];   // swizzled, 8 KB per stage
    __shared__ float    kms[2][64];

    const int tid  = threadIdx.x;
    const int w    = tid >> 5;
    const int lane = tid & 31;
    const int g    = lane >> 2;
    const int t    = lane & 3;
    const int r    = lane & 7;         // ldmatrix row-within-matrix

    const size_t headoff = (size_t)b * SEQ * HID + h * DH;
    const uint16_t* qbase = g_q + headoff;
    const uint16_t* kbase = g_k + headoff;
    const uint16_t* vbase = g_v + headoff;
    const float*    kmrow = g_kmask + b * SEQ;

    const int row_l = qt * 64 + w * 16 + g;   // this thread's frag row (local)

    const uint32_t ks_base  = (uint32_t)__cvta_generic_to_shared(&Ks[0][0]);
    const uint32_t vs_base  = (uint32_t)__cvta_generic_to_shared(&Vs[0][0]);
    const uint32_t kms_base = (uint32_t)__cvta_generic_to_shared(&kms[0][0]);

    // Fixed per-thread pieces of ldmatrix addressing
    const uint32_t k_sw = (uint32_t)((((lane >> 3) ^ r) & 7) << 4);
    const uint32_t k_addr0 = ks_base + (uint32_t)(r * 128) + k_sw;
    const int      v_keyoff = ((lane >> 3) & 1) * 8 + r;
    const uint32_t q2 = (uint32_t)(lane >> 4);

    // Per-thread cp.async slots: 4 x 16B chunks each for K and V
    int ld_row[4], ld_soff[4];
#pragma unroll
    for (int i = 0; i < 4; i++) {
        int idx = tid + i * 128;
        int row = idx >> 3;
        int c   = idx & 7;
        int swc = c ^ (row & 7);
        ld_row[i]  = row;
        ld_soff[i] = row * 128 + swc * 16;
    }

    // Q fragments: 4 k-steps of 16 over d=64, packed bf16 pairs
    uint32_t qf[4][4];
#pragma unroll
    for (int ks = 0; ks < 4; ks++) {
        int col = ks * 16 + 2 * t;
        qf[ks][0] = *(const uint32_t*)&qbase[(size_t)row_l * HID + col];
        qf[ks][1] = *(const uint32_t*)&qbase[(size_t)(row_l + 8) * HID + col];
        qf[ks][2] = *(const uint32_t*)&qbase[(size_t)row_l * HID + col + 8];
        qf[ks][3] = *(const uint32_t*)&qbase[(size_t)(row_l + 8) * HID + col + 8];
    }

    float o[8][4];
#pragma unroll
    for (int nt = 0; nt < 8; nt++)
#pragma unroll
        for (int c = 0; c < 4; c++) o[nt][c] = 0.f;

    float m0 = -3.0e38f, m1 = -3.0e38f, l0 = 0.f, l1 = 0.f;
    const float scale = 0.04419417382415922f;  // 1/sqrt(512)

    // ---- prologue: issue tile 0 into stage 0 ----
    {
#pragma unroll
        for (int i = 0; i < 4; i++) {
            size_t gofs = (size_t)(0 * 64 + ld_row[i]) * HID + (ld_soff[i] == 0 ? 0 : 0);
            // recompute column from slot (c*8 u16): c = (tid + i*128) & 7
            int c = (tid + i * 128) & 7;
            gofs = (size_t)ld_row[i] * HID + c * 8;
            CP_ASYNC_16(ks_base + (uint32_t)ld_soff[i], kbase + gofs);
            CP_ASYNC_16(vs_base + (uint32_t)ld_soff[i], vbase + gofs);
        }
        if (tid < 16) CP_ASYNC_16(kms_base + (uint32_t)(tid * 16), kmrow + tid * 4);
        CP_COMMIT();
    }

    for (int kt = 0; kt <= qt; kt++) {
        const int bfi = kt & 1;
        const uint32_t kofs = (uint32_t)(bfi * 8192);   // stage byte offset

        CP_WAIT_ALL();
        __syncthreads();

        // issue prefetch of tile kt+1 into the other stage
        if (kt < qt) {
            const uint32_t pofs = (uint32_t)((bfi ^ 1) * 8192);
#pragma unroll
            for (int i = 0; i < 4; i++) {
                int c = (tid + i * 128) & 7;
                size_t gofs = (size_t)((kt + 1) * 64 + ld_row[i]) * HID + c * 8;
                CP_ASYNC_16(ks_base + pofs + (uint32_t)ld_soff[i], kbase + gofs);
                CP_ASYNC_16(vs_base + pofs + (uint32_t)ld_soff[i], vbase + gofs);
            }
            if (tid < 16)
                CP_ASYNC_16(kms_base + (uint32_t)((bfi ^ 1) * 256 + tid * 16),
                            kmrow + (kt + 1) * 64 + tid * 4);
            CP_COMMIT();
        }

        // ---- S = Q K^T : per nt, two conflict-free ldmatrix.x4 ----
        float s[8][4];
#pragma unroll
        for (int nt = 0; nt < 8; nt++) {
            s[nt][0] = 0.f; s[nt][1] = 0.f; s[nt][2] = 0.f; s[nt][3] = 0.f;
            uint32_t base = k_addr0 + kofs + (uint32_t)(nt * 8 * 128);
            uint32_t b0, b1, b2, b3;
            LDSM_X4(b0, b1, b2, b3, base);          // k 0..31
            {
                uint32_t bf[2] = {b0, b1};
                MMA_BF16(s[nt], qf[0], bf);
                bf[0] = b2; bf[1] = b3;
                MMA_BF16(s[nt], qf[1], bf);
            }
            LDSM_X4(b0, b1, b2, b3, base ^ 64u);    // k 32..63
            {
                uint32_t bf[2] = {b0, b1};
                MMA_BF16(s[nt], qf[2], bf);
                bf[0] = b2; bf[1] = b3;
                MMA_BF16(s[nt], qf[3], bf);
            }
        }

        // ---- scale + masks (causal only on diagonal tile) ----
        const bool diag = (kt == qt);
#pragma unroll
        for (int nt = 0; nt < 8; nt++) {
            int c0 = nt * 8 + 2 * t;
            float km0 = kms[bfi][c0], km1 = kms[bfi][c0 + 1];
            int cg0 = kt * 64 + c0;
#pragma unroll
            for (int c = 0; c < 4; c++) {
                int colg = cg0 + (c & 1);
                int rowg = (c < 2) ? row_l : row_l + 8;
                float km = (c & 1) ? km1 : km0;
                float v = s[nt][c] * scale;
                if (km == 0.f || (diag && colg > rowg)) v = NEGV;
                s[nt][c] = v;
            }
        }

        // ---- online softmax on fragments ----
        float rm0 = -3.0e38f, rm1 = -3.0e38f;
#pragma unroll
        for (int nt = 0; nt < 8; nt++) {
            rm0 = fmaxf(rm0, fmaxf(s[nt][0], s[nt][1]));
            rm1 = fmaxf(rm1, fmaxf(s[nt][2], s[nt][3]));
        }
        rm0 = fmaxf(rm0, __shfl_xor_sync(0xFFFFFFFFu, rm0, 1));
        rm0 = fmaxf(rm0, __shfl_xor_sync(0xFFFFFFFFu, rm0, 2));
        rm1 = fmaxf(rm1, __shfl_xor_sync(0xFFFFFFFFu, rm1, 1));
        rm1 = fmaxf(rm1, __shfl_xor_sync(0xFFFFFFFFu, rm1, 2));

        float mn0 = fmaxf(m0, rm0);
        float mn1 = fmaxf(m1, rm1);
        float rs0 = 0.f, rs1 = 0.f;
#pragma unroll
        for (int nt = 0; nt < 8; nt++) {
            s[nt][0] = __expf(s[nt][0] - mn0);
            s[nt][1] = __expf(s[nt][1] - mn0);
            s[nt][2] = __expf(s[nt][2] - mn1);
            s[nt][3] = __expf(s[nt][3] - mn1);
            rs0 += s[nt][0] + s[nt][1];
            rs1 += s[nt][2] + s[nt][3];
        }
        rs0 += __shfl_xor_sync(0xFFFFFFFFu, rs0, 1);
        rs0 += __shfl_xor_sync(0xFFFFFFFFu, rs0, 2);
        rs1 += __shfl_xor_sync(0xFFFFFFFFu, rs1, 1);
        rs1 += __shfl_xor_sync(0xFFFFFFFFu, rs1, 2);

        float sc0 = __expf(m0 - mn0);
        float sc1 = __expf(m1 - mn1);
        l0 = l0 * sc0 + rs0;
        l1 = l1 * sc1 + rs1;
        m0 = mn0; m1 = mn1;
#pragma unroll
        for (int nt = 0; nt < 8; nt++) {
            o[nt][0] *= sc0; o[nt][1] *= sc0;
            o[nt][2] *= sc1; o[nt][3] *= sc1;
        }

        // ---- O += P V : A-frag = repacked S; B via trans ldmatrix.x4 ------
#pragma unroll
        for (int kc = 0; kc < 4; kc++) {
            uint32_t pa[4];
            pa[0] = pack_bf16(s[2 * kc][0],     s[2 * kc][1]);
            pa[1] = pack_bf16(s[2 * kc][2],     s[2 * kc][3]);
            pa[2] = pack_bf16(s[2 * kc + 1][0], s[2 * kc + 1][1]);
            pa[3] = pack_bf16(s[2 * kc + 1][2], s[2 * kc + 1][3]);
            uint32_t vrow = vs_base + kofs + (uint32_t)((kc * 16 + v_keyoff) * 128);
#pragma unroll
            for (int half = 0; half < 4; half++) {   // d-chunk = 2*half + q2
                uint32_t addr = vrow +
                    (uint32_t)(((((uint32_t)(half << 1) | q2) ^ (uint32_t)r) & 7u) << 4);
                uint32_t b0, b1, b2, b3;
                LDSM_X4_T(b0, b1, b2, b3, addr);
                uint32_t bf[2] = {b0, b1};
                MMA_BF16(o[half * 2], pa, bf);
                bf[0] = b2; bf[1] = b3;
                MMA_BF16(o[half * 2 + 1], pa, bf);
            }
        }
    }

    // ---- epilogue: normalize, query-mask, residual, store ----
    const int grow0 = b * SEQ + row_l;
    const float fac0 = (1.0f / l0) * g_qmask[grow0];
    const float fac1 = (1.0f / l1) * g_qmask[grow0 + 8];
#pragma unroll
    for (int nt2 = 0; nt2 < 8; nt2++) {
        int col = h * DH + nt2 * 8 + 2 * t;
        size_t a0 = (size_t)grow0 * HID + col;
        size_t a1 = (size_t)(grow0 + 8) * HID + col;
        float2 lo = make_float2(o[nt2][0] * fac0 + queries[a0],
                                o[nt2][1] * fac0 + queries[a0 + 1]);
        float2 hi = make_float2(o[nt2][2] * fac1 + queries[a1],
                                o[nt2][3] * fac1 + queries[a1 + 1]);
        *(float2*)&out[a0] = lo;
        *(float2*)&out[a1] = hi;
    }
}

// ---------------- launcher --------------------------------------------------
extern "C" void kernel_launch(void* const* d_in, const int* in_sizes, int n_in,
                              void* d_out, int out_size) {
    const float* queries = (const float*)d_in[0];
    const float* keys    = (const float*)d_in[1];
    const float* Wq      = (const float*)d_in[2];
    const float* bq      = (const float*)d_in[3];
    const float* Wk      = (const float*)d_in[4];
    const float* bk      = (const float*)d_in[5];
    const float* Wv      = (const float*)d_in[6];
    const float* bv      = (const float*)d_in[7];
    float* out = (float*)d_out;

    mask_kernel<<<(2 * ROWS) / 8, 256>>>(queries, keys);

    gemm_qkv<<<dim3(HID / 128, ROWS / 128, 3), 256>>>(queries, keys,
                                                      Wq, bq, Wk, bk, Wv, bv);

    attn_kernel<<<dim3(SEQ / 64, BATCH, NH), 128>>>(queries, out);
}